// round 7
// baseline (speedup 1.0000x reference)
#include <cuda_runtime.h>
#include <cuda_bf16.h>
#include <cstdint>

#define NN      8192
#define F_IN    512
#define NOUT    64
#define LRA     0.2f
#define JSPLITS 8
#define JLEN    (NN / JSPLITS)     // 1024
#define NCH     (JLEN / 16)        // 64 chunks of k=16

// ---------------- device scratch (no cudaMalloc allowed) -------------------
__device__ uint4 g_W_pk[64 * 32 * 4];         // 128 KB
__device__ uint4 g_WhT_pk[64 * 512 * 4];      // 2 MB
__device__ float g_e1[NN];
__device__ float g_e2[NN];
__device__ float g_pacc[JSPLITS][NN][NOUT];
__device__ float g_pden[JSPLITS][NN];

// ---------------- helpers ---------------------------------------------------
__device__ __forceinline__ void mma16816(float* d, const unsigned* a,
                                         unsigned b0, unsigned b1) {
    asm volatile(
        "mma.sync.aligned.m16n8k16.row.col.f32.bf16.bf16.f32 "
        "{%0,%1,%2,%3}, {%4,%5,%6,%7}, {%8,%9}, {%0,%1,%2,%3};"
        : "+f"(d[0]), "+f"(d[1]), "+f"(d[2]), "+f"(d[3])
        : "r"(a[0]), "r"(a[1]), "r"(a[2]), "r"(a[3]), "r"(b0), "r"(b1));
}
__device__ __forceinline__ unsigned cvt2(float po, float pe) {   // hi=po, lo=pe
    unsigned r;
    asm("cvt.rn.bf16x2.f32 %0, %1, %2;" : "=r"(r) : "f"(po), "f"(pe));
    return r;
}
__device__ __forceinline__ float bfhf(float x) {
    return __bfloat162float(__float2bfloat16_rn(x));
}
__device__ __forceinline__ uint32_t smem_u32(const void* p) {
    return (uint32_t)__cvta_generic_to_shared(p);
}
__device__ __forceinline__ void cpa16(uint32_t dst, const void* src) {
    asm volatile("cp.async.cg.shared.global [%0], [%1], 16;" :: "r"(dst), "l"(src));
}
__device__ __forceinline__ void cpcommit() {
    asm volatile("cp.async.commit_group;" ::: "memory");
}
template <int N> __device__ __forceinline__ void cpwait() {
    asm volatile("cp.async.wait_group %0;" :: "n"(N) : "memory");
}

// ---------------------------------------------------------------------------
// Kernel 0: pack W (fp32 [512][64]) into bf16 hi/lo fragment layout.
// ---------------------------------------------------------------------------
__global__ void __launch_bounds__(256) prep_w(const float* __restrict__ W) {
    const int t = blockIdx.x * 256 + threadIdx.x;
    const int s = t & 3, kc = (t >> 2) & 31, n = t >> 7;
    const int k0 = kc * 16 + 2 * s;
    float v00 = W[(k0 + 0) * 64 + n], v01 = W[(k0 + 1) * 64 + n];
    float v10 = W[(k0 + 8) * 64 + n], v11 = W[(k0 + 9) * 64 + n];
    float h00 = bfhf(v00), h01 = bfhf(v01), h10 = bfhf(v10), h11 = bfhf(v11);
    uint4 o;
    o.x = cvt2(h01, h00);
    o.y = cvt2(h11, h10);
    o.z = cvt2(v01 - h01, v00 - h00);
    o.w = cvt2(v11 - h11, v10 - h10);
    g_W_pk[(n * 32 + kc) * 4 + s] = o;
}

// ---------------------------------------------------------------------------
// Kernel 1: Wh = h @ W via mma.sync (3-product bf16 split). (unchanged R6)
// ---------------------------------------------------------------------------
__global__ void __launch_bounds__(128, 1) wh_mma(const float* __restrict__ h,
                                                 const float* __restrict__ a) {
    __shared__ float s_h[3][64][20];
    __shared__ float s_t[64][65];

    const int tid = threadIdx.x;
    const int w = tid >> 5;
    const int l = tid & 31;
    const int r = l >> 2;
    const int c = (l & 3) * 2;
    const int node0 = blockIdx.x * 64;

    const uint32_t shb = smem_u32(&s_h[0][0][0]);
    auto stage = [&](int kc, int s) {
        const int row = tid >> 1, half = tid & 1;
        const float* src = h + (size_t)(node0 + row) * F_IN + kc * 16 + half * 8;
        uint32_t dst = shb + (uint32_t)((s * 64 + row) * 20 + half * 8) * 4;
        cpa16(dst, src);
        cpa16(dst + 16, src + 4);
    };

    stage(0, 0); cpcommit();
    stage(1, 1); cpcommit();

    float acc[8][4];
#pragma unroll
    for (int n = 0; n < 8; ++n)
#pragma unroll
        for (int q = 0; q < 4; ++q) acc[n][q] = 0.f;

    const uint4* __restrict__ wpk = g_W_pk;

    for (int kc = 0; kc < 32; ++kc) {
        const int ss = kc % 3;
        if (kc + 1 < 32) cpwait<1>(); else cpwait<0>();
        __syncthreads();
        if (kc + 2 < 32) { stage(kc + 2, (kc + 2) % 3); cpcommit(); }

        uint4 B4[8];
#pragma unroll
        for (int nt = 0; nt < 8; ++nt)
            B4[nt] = wpk[((nt * 8 + r) * 32 + kc) * 4 + (l & 3)];

        float2 v0 = *(const float2*)&s_h[ss][w * 16 + r][c];
        float2 v1 = *(const float2*)&s_h[ss][w * 16 + r + 8][c];
        float2 v2 = *(const float2*)&s_h[ss][w * 16 + r][c + 8];
        float2 v3 = *(const float2*)&s_h[ss][w * 16 + r + 8][c + 8];
        float h0x = bfhf(v0.x), h0y = bfhf(v0.y);
        float h1x = bfhf(v1.x), h1y = bfhf(v1.y);
        float h2x = bfhf(v2.x), h2y = bfhf(v2.y);
        float h3x = bfhf(v3.x), h3y = bfhf(v3.y);
        unsigned Ah[4], Al[4];
        Ah[0] = cvt2(h0y, h0x); Al[0] = cvt2(v0.y - h0y, v0.x - h0x);
        Ah[1] = cvt2(h1y, h1x); Al[1] = cvt2(v1.y - h1y, v1.x - h1x);
        Ah[2] = cvt2(h2y, h2x); Al[2] = cvt2(v2.y - h2y, v2.x - h2x);
        Ah[3] = cvt2(h3y, h3x); Al[3] = cvt2(v3.y - h3y, v3.x - h3x);

#pragma unroll
        for (int nt = 0; nt < 8; ++nt) mma16816(acc[nt], Ah, B4[nt].x, B4[nt].y);
#pragma unroll
        for (int nt = 0; nt < 8; ++nt) mma16816(acc[nt], Al, B4[nt].x, B4[nt].y);
#pragma unroll
        for (int nt = 0; nt < 8; ++nt) mma16816(acc[nt], Ah, B4[nt].z, B4[nt].w);
    }

    {
        float e1p0 = 0.f, e1p8 = 0.f, e2p0 = 0.f, e2p8 = 0.f;
#pragma unroll
        for (int nt = 0; nt < 8; ++nt) {
            float2 a1v = *(const float2*)&a[nt * 8 + c];
            float2 a2v = *(const float2*)&a[NOUT + nt * 8 + c];
            e1p0 += acc[nt][0] * a1v.x + acc[nt][1] * a1v.y;
            e1p8 += acc[nt][2] * a1v.x + acc[nt][3] * a1v.y;
            e2p0 += acc[nt][0] * a2v.x + acc[nt][1] * a2v.y;
            e2p8 += acc[nt][2] * a2v.x + acc[nt][3] * a2v.y;
        }
#pragma unroll
        for (int off = 1; off <= 2; off <<= 1) {
            e1p0 += __shfl_xor_sync(0xffffffffu, e1p0, off);
            e1p8 += __shfl_xor_sync(0xffffffffu, e1p8, off);
            e2p0 += __shfl_xor_sync(0xffffffffu, e2p0, off);
            e2p8 += __shfl_xor_sync(0xffffffffu, e2p8, off);
        }
        if ((l & 3) == 0) {
            g_e1[node0 + w * 16 + r]     = e1p0;
            g_e1[node0 + w * 16 + r + 8] = e1p8;
            g_e2[node0 + w * 16 + r]     = e2p0;
            g_e2[node0 + w * 16 + r + 8] = e2p8;
        }
    }

    __syncthreads();
#pragma unroll
    for (int nt = 0; nt < 8; ++nt) {
        s_t[w * 16 + r][nt * 8 + c]         = acc[nt][0];
        s_t[w * 16 + r][nt * 8 + c + 1]     = acc[nt][1];
        s_t[w * 16 + r + 8][nt * 8 + c]     = acc[nt][2];
        s_t[w * 16 + r + 8][nt * 8 + c + 1] = acc[nt][3];
    }
    __syncthreads();

    {
        const int col = tid >> 1, nh = tid & 1;
        float f[32];
#pragma unroll
        for (int j = 0; j < 32; ++j) f[j] = s_t[nh * 32 + j][col];
#pragma unroll
        for (int q = 0; q < 2; ++q) {
            const int chg = blockIdx.x * 4 + nh * 2 + q;
            const int jo = q * 16;
#pragma unroll
            for (int s = 0; s < 4; ++s) {
                float f0 = f[jo + 2 * s],     f1 = f[jo + 2 * s + 1];
                float f8 = f[jo + 2 * s + 8], f9 = f[jo + 2 * s + 9];
                float g0 = bfhf(f0), g1 = bfhf(f1), g8 = bfhf(f8), g9 = bfhf(f9);
                uint4 o;
                o.x = cvt2(g1, g0);
                o.y = cvt2(g9, g8);
                o.z = cvt2(f1 - g1, f0 - g0);
                o.w = cvt2(f9 - g9, f8 - g8);
                g_WhT_pk[(col * 512 + chg) * 4 + s] = o;
            }
        }
    }
}

// ---------------------------------------------------------------------------
// Kernel 2: fused masked-exp + bf16 split GEMM, barrier-free main loop,
// A-generation software-pipelined ONE CHUNK AHEAD of its MMA consumption:
// while the tensor pipe runs chunk ch's 24 HMMAs, the fma/mufu pipes build
// chunk ch+1's P fragments (independent registers -> full overlap).
// ---------------------------------------------------------------------------
__global__ void __launch_bounds__(256, 2) attn_kernel(const int* __restrict__ adj) {
    __shared__ float s_e2[JLEN];    // 4 KB

    const int tid = threadIdx.x;
    const int w = tid >> 5;
    const int l = tid & 31;
    const int i0 = (int)(blockIdx.x >> 3) * 128;
    const int split = blockIdx.x & 7;
    const int j0 = split * JLEN;

    {
        float4* d = (float4*)s_e2;
        const float4* s = (const float4*)(g_e2 + j0);
        for (int k = tid; k < JLEN / 4; k += 256) d[k] = s[k];
    }

    const int rq = l >> 2;          // 0..7
    const int cq = (l & 3) * 2;     // 0,2,4,6

    float e1r[2];
    const int* rb[2];
#pragma unroll
    for (int k = 0; k < 2; ++k) {
        int row = i0 + w * 16 + 8 * k + rq;
        e1r[k] = g_e1[row];
        rb[k] = adj + (size_t)row * NN + j0 + cq;
    }

    const uint4* __restrict__ bp =
        g_WhT_pk + (size_t)rq * 2048 + (l & 3) + (size_t)split * 256;

    float acc[8][4];
#pragma unroll
    for (int n = 0; n < 8; ++n)
#pragma unroll
        for (int q = 0; q < 4; ++q) acc[n][q] = 0.f;
    float den2[2] = {0.f, 0.f};

    int2 alo[2], ahi[2];
    // generate P fragments for chunk ch from adj regs + e2 smem
    auto genA = [&](int ch, unsigned* Ah, unsigned* Al) {
        const float* e2p = s_e2 + ch * 16;
        float2 e2a = *(const float2*)(e2p + cq);
        float2 e2b = *(const float2*)(e2p + cq + 8);
#pragma unroll
        for (int k = 0; k < 2; ++k) {
            const float e1v = e1r[k];
            float s0 = e1v + e2a.x; s0 = s0 > 0.f ? s0 : LRA * s0;
            float s1 = e1v + e2a.y; s1 = s1 > 0.f ? s1 : LRA * s1;
            float s2 = e1v + e2b.x; s2 = s2 > 0.f ? s2 : LRA * s2;
            float s3 = e1v + e2b.y; s3 = s3 > 0.f ? s3 : LRA * s3;
            float p0 = alo[k].x > 0 ? __expf(s0) : 0.f;
            float p1 = alo[k].y > 0 ? __expf(s1) : 0.f;
            float p2 = ahi[k].x > 0 ? __expf(s2) : 0.f;
            float p3 = ahi[k].y > 0 ? __expf(s3) : 0.f;
            den2[k] += (p0 + p1) + (p2 + p3);
            float h0 = bfhf(p0), h1 = bfhf(p1), h2 = bfhf(p2), h3 = bfhf(p3);
            Ah[k]     = cvt2(h1, h0);
            Ah[k + 2] = cvt2(h3, h2);
            Al[k]     = cvt2(p1 - h1, p0 - h0);
            Al[k + 2] = cvt2(p3 - h3, p2 - h2);
        }
    };
    auto loadAdj = [&](int ch) {
#pragma unroll
        for (int k = 0; k < 2; ++k) {
            alo[k] = *(const int2*)(rb[k] + ch * 16);
            ahi[k] = *(const int2*)(rb[k] + ch * 16 + 8);
        }
    };

    unsigned A0h[4], A0l[4], A1h[4], A1l[4];

    loadAdj(0);
    __syncthreads();                 // e2 visible; only barrier in the kernel
    genA(0, A0h, A0l);               // A(0)
    loadAdj(1);

#pragma unroll 2
    for (int ch = 0; ch < NCH; ++ch) {
        unsigned* curH = (ch & 1) ? A1h : A0h;
        unsigned* curL = (ch & 1) ? A1l : A0l;
        unsigned* nxtH = (ch & 1) ? A0h : A1h;
        unsigned* nxtL = (ch & 1) ? A0l : A1l;

        // B frags for chunk ch: 8 x LDG.128 (L1-resident)
        uint4 B4[8];
#pragma unroll
        for (int nt = 0; nt < 8; ++nt) B4[nt] = bp[nt * 16384 + ch * 4];

        // build A(ch+1) — overlaps with the MMAs below (independent regs)
        if (ch + 1 < NCH) genA(ch + 1, nxtH, nxtL);
        if (ch + 2 < NCH) loadAdj(ch + 2);

        // consume A(ch)
#pragma unroll
        for (int nt = 0; nt < 8; ++nt) mma16816(acc[nt], curH, B4[nt].x, B4[nt].y);
#pragma unroll
        for (int nt = 0; nt < 8; ++nt) mma16816(acc[nt], curL, B4[nt].x, B4[nt].y);
#pragma unroll
        for (int nt = 0; nt < 8; ++nt) mma16816(acc[nt], curH, B4[nt].z, B4[nt].w);
    }

    // ---- denominators: quad-reduce per row ----
#pragma unroll
    for (int k = 0; k < 2; ++k) {
        den2[k] += __shfl_xor_sync(0xffffffffu, den2[k], 1);
        den2[k] += __shfl_xor_sync(0xffffffffu, den2[k], 2);
    }
    if ((l & 3) == 0) {
        g_pden[split][i0 + w * 16 + rq]     = den2[0];
        g_pden[split][i0 + w * 16 + 8 + rq] = den2[1];
    }

    // ---- write fp32 partial numerators ----
    {
        const int row = i0 + w * 16 + rq;
#pragma unroll
        for (int n = 0; n < 8; ++n) {
            *(float2*)&g_pacc[split][row][n * 8 + cq]     = make_float2(acc[n][0], acc[n][1]);
            *(float2*)&g_pacc[split][row + 8][n * 8 + cq] = make_float2(acc[n][2], acc[n][3]);
        }
    }
}

// ---------------------------------------------------------------------------
// Kernel 3: combine splits, normalize, ELU.
// ---------------------------------------------------------------------------
__global__ void __launch_bounds__(256) combine_kernel(float* __restrict__ out) {
    const int idx = blockIdx.x * 256 + threadIdx.x;   // over 8192*64
    const int i = idx >> 6;
    const int c = idx & 63;
    float acc = 0.f, den = 0.f;
#pragma unroll
    for (int sp = 0; sp < JSPLITS; ++sp) {
        acc += g_pacc[sp][i][c];
        den += g_pden[sp][i];
    }
    if (den == 0.f) den = 1.f;
    float v = acc / den;
    out[idx] = v > 0.f ? v : expm1f(v);
}

// ---------------------------------------------------------------------------
extern "C" void kernel_launch(void* const* d_in, const int* in_sizes, int n_in,
                              void* d_out, int out_size) {
    const float* h   = (const float*)d_in[0];
    const float* W   = (const float*)d_in[1];
    const float* a   = (const float*)d_in[2];
    const int*   adj = (const int*)d_in[3];
    float* out = (float*)d_out;

    prep_w<<<32, 256>>>(W);
    wh_mma<<<128, 128>>>(h, a);
    attn_kernel<<<(NN / 128) * JSPLITS, 256>>>(adj);
    combine_kernel<<<NN * NOUT / 256, 256>>>(out);
}

// round 8
// speedup vs baseline: 1.0463x; 1.0463x over previous
#include <cuda_runtime.h>
#include <cuda_bf16.h>
#include <cstdint>

#define NN      8192
#define F_IN    512
#define NOUT    64
#define LRA     0.2f
#define JSPLITS 8
#define JLEN    (NN / JSPLITS)     // 1024
#define NCH     (JLEN / 16)        // 64 chunks of k=16

// ---------------- device scratch (no cudaMalloc allowed) -------------------
__device__ uint4 g_W_pk[64 * 32 * 4];         // 128 KB
// Fragment-packed WhT, CHUNK-MAJOR: [512 jchunk][64 n][4 s] uint4.
// Per-lane fragment index = chg*256 + nt*32 + lane  -> fully coalesced LDG.128.
__device__ uint4 g_WhT_pk[512 * 64 * 4];      // 2 MB
__device__ float g_e1[NN];
__device__ float g_e2[NN];
__device__ float g_pacc[JSPLITS][NN][NOUT];
__device__ float g_pden[JSPLITS][NN];

// ---------------- helpers ---------------------------------------------------
__device__ __forceinline__ void mma16816(float* d, const unsigned* a,
                                         unsigned b0, unsigned b1) {
    asm volatile(
        "mma.sync.aligned.m16n8k16.row.col.f32.bf16.bf16.f32 "
        "{%0,%1,%2,%3}, {%4,%5,%6,%7}, {%8,%9}, {%0,%1,%2,%3};"
        : "+f"(d[0]), "+f"(d[1]), "+f"(d[2]), "+f"(d[3])
        : "r"(a[0]), "r"(a[1]), "r"(a[2]), "r"(a[3]), "r"(b0), "r"(b1));
}
__device__ __forceinline__ unsigned cvt2(float po, float pe) {   // hi=po, lo=pe
    unsigned r;
    asm("cvt.rn.bf16x2.f32 %0, %1, %2;" : "=r"(r) : "f"(po), "f"(pe));
    return r;
}
__device__ __forceinline__ float bfhf(float x) {
    return __bfloat162float(__float2bfloat16_rn(x));
}
__device__ __forceinline__ uint32_t smem_u32(const void* p) {
    return (uint32_t)__cvta_generic_to_shared(p);
}
__device__ __forceinline__ void cpa16(uint32_t dst, const void* src) {
    asm volatile("cp.async.cg.shared.global [%0], [%1], 16;" :: "r"(dst), "l"(src));
}
__device__ __forceinline__ void cpcommit() {
    asm volatile("cp.async.commit_group;" ::: "memory");
}
template <int N> __device__ __forceinline__ void cpwait() {
    asm volatile("cp.async.wait_group %0;" :: "n"(N) : "memory");
}

// ---------------------------------------------------------------------------
// Kernel 0: pack W (fp32 [512][64]) into bf16 hi/lo fragment layout.
// ---------------------------------------------------------------------------
__global__ void __launch_bounds__(256) prep_w(const float* __restrict__ W) {
    const int t = blockIdx.x * 256 + threadIdx.x;
    const int s = t & 3, kc = (t >> 2) & 31, n = t >> 7;
    const int k0 = kc * 16 + 2 * s;
    float v00 = W[(k0 + 0) * 64 + n], v01 = W[(k0 + 1) * 64 + n];
    float v10 = W[(k0 + 8) * 64 + n], v11 = W[(k0 + 9) * 64 + n];
    float h00 = bfhf(v00), h01 = bfhf(v01), h10 = bfhf(v10), h11 = bfhf(v11);
    uint4 o;
    o.x = cvt2(h01, h00);
    o.y = cvt2(h11, h10);
    o.z = cvt2(v01 - h01, v00 - h00);
    o.w = cvt2(v11 - h11, v10 - h10);
    g_W_pk[(n * 32 + kc) * 4 + s] = o;
}

// ---------------------------------------------------------------------------
// Kernel 1: Wh = h @ W via mma.sync (3-product bf16 split).
// Epilogue writes chunk-major g_WhT_pk.
// ---------------------------------------------------------------------------
__global__ void __launch_bounds__(128, 1) wh_mma(const float* __restrict__ h,
                                                 const float* __restrict__ a) {
    __shared__ float s_h[3][64][20];
    __shared__ float s_t[64][65];

    const int tid = threadIdx.x;
    const int w = tid >> 5;
    const int l = tid & 31;
    const int r = l >> 2;
    const int c = (l & 3) * 2;
    const int node0 = blockIdx.x * 64;

    const uint32_t shb = smem_u32(&s_h[0][0][0]);
    auto stage = [&](int kc, int s) {
        const int row = tid >> 1, half = tid & 1;
        const float* src = h + (size_t)(node0 + row) * F_IN + kc * 16 + half * 8;
        uint32_t dst = shb + (uint32_t)((s * 64 + row) * 20 + half * 8) * 4;
        cpa16(dst, src);
        cpa16(dst + 16, src + 4);
    };

    stage(0, 0); cpcommit();
    stage(1, 1); cpcommit();

    float acc[8][4];
#pragma unroll
    for (int n = 0; n < 8; ++n)
#pragma unroll
        for (int q = 0; q < 4; ++q) acc[n][q] = 0.f;

    const uint4* __restrict__ wpk = g_W_pk;

    for (int kc = 0; kc < 32; ++kc) {
        const int ss = kc % 3;
        if (kc + 1 < 32) cpwait<1>(); else cpwait<0>();
        __syncthreads();
        if (kc + 2 < 32) { stage(kc + 2, (kc + 2) % 3); cpcommit(); }

        uint4 B4[8];
#pragma unroll
        for (int nt = 0; nt < 8; ++nt)
            B4[nt] = wpk[((nt * 8 + r) * 32 + kc) * 4 + (l & 3)];

        float2 v0 = *(const float2*)&s_h[ss][w * 16 + r][c];
        float2 v1 = *(const float2*)&s_h[ss][w * 16 + r + 8][c];
        float2 v2 = *(const float2*)&s_h[ss][w * 16 + r][c + 8];
        float2 v3 = *(const float2*)&s_h[ss][w * 16 + r + 8][c + 8];
        float h0x = bfhf(v0.x), h0y = bfhf(v0.y);
        float h1x = bfhf(v1.x), h1y = bfhf(v1.y);
        float h2x = bfhf(v2.x), h2y = bfhf(v2.y);
        float h3x = bfhf(v3.x), h3y = bfhf(v3.y);
        unsigned Ah[4], Al[4];
        Ah[0] = cvt2(h0y, h0x); Al[0] = cvt2(v0.y - h0y, v0.x - h0x);
        Ah[1] = cvt2(h1y, h1x); Al[1] = cvt2(v1.y - h1y, v1.x - h1x);
        Ah[2] = cvt2(h2y, h2x); Al[2] = cvt2(v2.y - h2y, v2.x - h2x);
        Ah[3] = cvt2(h3y, h3x); Al[3] = cvt2(v3.y - h3y, v3.x - h3x);

#pragma unroll
        for (int nt = 0; nt < 8; ++nt) mma16816(acc[nt], Ah, B4[nt].x, B4[nt].y);
#pragma unroll
        for (int nt = 0; nt < 8; ++nt) mma16816(acc[nt], Al, B4[nt].x, B4[nt].y);
#pragma unroll
        for (int nt = 0; nt < 8; ++nt) mma16816(acc[nt], Ah, B4[nt].z, B4[nt].w);
    }

    {
        float e1p0 = 0.f, e1p8 = 0.f, e2p0 = 0.f, e2p8 = 0.f;
#pragma unroll
        for (int nt = 0; nt < 8; ++nt) {
            float2 a1v = *(const float2*)&a[nt * 8 + c];
            float2 a2v = *(const float2*)&a[NOUT + nt * 8 + c];
            e1p0 += acc[nt][0] * a1v.x + acc[nt][1] * a1v.y;
            e1p8 += acc[nt][2] * a1v.x + acc[nt][3] * a1v.y;
            e2p0 += acc[nt][0] * a2v.x + acc[nt][1] * a2v.y;
            e2p8 += acc[nt][2] * a2v.x + acc[nt][3] * a2v.y;
        }
#pragma unroll
        for (int off = 1; off <= 2; off <<= 1) {
            e1p0 += __shfl_xor_sync(0xffffffffu, e1p0, off);
            e1p8 += __shfl_xor_sync(0xffffffffu, e1p8, off);
            e2p0 += __shfl_xor_sync(0xffffffffu, e2p0, off);
            e2p8 += __shfl_xor_sync(0xffffffffu, e2p8, off);
        }
        if ((l & 3) == 0) {
            g_e1[node0 + w * 16 + r]     = e1p0;
            g_e1[node0 + w * 16 + r + 8] = e1p8;
            g_e2[node0 + w * 16 + r]     = e2p0;
            g_e2[node0 + w * 16 + r + 8] = e2p8;
        }
    }

    __syncthreads();
#pragma unroll
    for (int nt = 0; nt < 8; ++nt) {
        s_t[w * 16 + r][nt * 8 + c]         = acc[nt][0];
        s_t[w * 16 + r][nt * 8 + c + 1]     = acc[nt][1];
        s_t[w * 16 + r + 8][nt * 8 + c]     = acc[nt][2];
        s_t[w * 16 + r + 8][nt * 8 + c + 1] = acc[nt][3];
    }
    __syncthreads();

    {
        const int col = tid >> 1, nh = tid & 1;   // col = n (0..63)
        float f[32];
#pragma unroll
        for (int j = 0; j < 32; ++j) f[j] = s_t[nh * 32 + j][col];
#pragma unroll
        for (int q = 0; q < 2; ++q) {
            const int chg = blockIdx.x * 4 + nh * 2 + q;
            const int jo = q * 16;
#pragma unroll
            for (int s = 0; s < 4; ++s) {
                float f0 = f[jo + 2 * s],     f1 = f[jo + 2 * s + 1];
                float f8 = f[jo + 2 * s + 8], f9 = f[jo + 2 * s + 9];
                float g0 = bfhf(f0), g1 = bfhf(f1), g8 = bfhf(f8), g9 = bfhf(f9);
                uint4 o;
                o.x = cvt2(g1, g0);
                o.y = cvt2(g9, g8);
                o.z = cvt2(f1 - g1, f0 - g0);
                o.w = cvt2(f9 - g9, f8 - g8);
                g_WhT_pk[(chg * 64 + col) * 4 + s] = o;   // chunk-major
            }
        }
    }
}

// ---------------------------------------------------------------------------
// Kernel 2: fused masked-exp + bf16 split GEMM, barrier-free main loop.
// B: one fully-coalesced LDG.128 per n-tile per chunk (512B contiguous,
// identical addresses across the CTA's 8 warps -> L1 broadcast hits).
// A generated one chunk ahead; adj prefetched two ahead.
// ---------------------------------------------------------------------------
__global__ void __launch_bounds__(256, 2) attn_kernel(const int* __restrict__ adj) {
    __shared__ float s_e2[JLEN];    // 4 KB

    const int tid = threadIdx.x;
    const int w = tid >> 5;
    const int l = tid & 31;
    const int i0 = (int)(blockIdx.x >> 3) * 128;
    const int split = blockIdx.x & 7;
    const int j0 = split * JLEN;

    {
        float4* d = (float4*)s_e2;
        const float4* s = (const float4*)(g_e2 + j0);
        for (int k = tid; k < JLEN / 4; k += 256) d[k] = s[k];
    }

    const int rq = l >> 2;          // 0..7
    const int cq = (l & 3) * 2;     // 0,2,4,6

    float e1r[2];
    const int* rb[2];
#pragma unroll
    for (int k = 0; k < 2; ++k) {
        int row = i0 + w * 16 + 8 * k + rq;
        e1r[k] = g_e1[row];
        rb[k] = adj + (size_t)row * NN + j0 + cq;
    }

    // chunk-major lane pointer: index = (split*64 + ch)*256 + nt*32 + l
    const uint4* __restrict__ bp = g_WhT_pk + (size_t)split * 64 * 256 + l;

    float acc[8][4];
#pragma unroll
    for (int n = 0; n < 8; ++n)
#pragma unroll
        for (int q = 0; q < 4; ++q) acc[n][q] = 0.f;
    float den2[2] = {0.f, 0.f};

    int2 alo[2], ahi[2];
    auto genA = [&](int ch, unsigned* Ah, unsigned* Al) {
        const float* e2p = s_e2 + ch * 16;
        float2 e2a = *(const float2*)(e2p + cq);
        float2 e2b = *(const float2*)(e2p + cq + 8);
#pragma unroll
        for (int k = 0; k < 2; ++k) {
            const float e1v = e1r[k];
            float s0 = e1v + e2a.x; s0 = s0 > 0.f ? s0 : LRA * s0;
            float s1 = e1v + e2a.y; s1 = s1 > 0.f ? s1 : LRA * s1;
            float s2 = e1v + e2b.x; s2 = s2 > 0.f ? s2 : LRA * s2;
            float s3 = e1v + e2b.y; s3 = s3 > 0.f ? s3 : LRA * s3;
            float p0 = alo[k].x > 0 ? __expf(s0) : 0.f;
            float p1 = alo[k].y > 0 ? __expf(s1) : 0.f;
            float p2 = ahi[k].x > 0 ? __expf(s2) : 0.f;
            float p3 = ahi[k].y > 0 ? __expf(s3) : 0.f;
            den2[k] += (p0 + p1) + (p2 + p3);
            float h0 = bfhf(p0), h1 = bfhf(p1), h2 = bfhf(p2), h3 = bfhf(p3);
            Ah[k]     = cvt2(h1, h0);
            Ah[k + 2] = cvt2(h3, h2);
            Al[k]     = cvt2(p1 - h1, p0 - h0);
            Al[k + 2] = cvt2(p3 - h3, p2 - h2);
        }
    };
    auto loadAdj = [&](int ch) {
#pragma unroll
        for (int k = 0; k < 2; ++k) {
            alo[k] = *(const int2*)(rb[k] + ch * 16);
            ahi[k] = *(const int2*)(rb[k] + ch * 16 + 8);
        }
    };

    unsigned A0h[4], A0l[4], A1h[4], A1l[4];

    loadAdj(0);
    __syncthreads();                 // e2 visible; only barrier in the kernel
    genA(0, A0h, A0l);
    loadAdj(1);

#pragma unroll 2
    for (int ch = 0; ch < NCH; ++ch) {
        unsigned* curH = (ch & 1) ? A1h : A0h;
        unsigned* curL = (ch & 1) ? A1l : A0l;
        unsigned* nxtH = (ch & 1) ? A0h : A1h;
        unsigned* nxtL = (ch & 1) ? A0l : A1l;

        // B frags: 8 coalesced LDG.128 (contiguous 512B each)
        uint4 B4[8];
#pragma unroll
        for (int nt = 0; nt < 8; ++nt) B4[nt] = bp[ch * 256 + nt * 32];

        if (ch + 1 < NCH) genA(ch + 1, nxtH, nxtL);
        if (ch + 2 < NCH) loadAdj(ch + 2);

#pragma unroll
        for (int nt = 0; nt < 8; ++nt) mma16816(acc[nt], curH, B4[nt].x, B4[nt].y);
#pragma unroll
        for (int nt = 0; nt < 8; ++nt) mma16816(acc[nt], curL, B4[nt].x, B4[nt].y);
#pragma unroll
        for (int nt = 0; nt < 8; ++nt) mma16816(acc[nt], curH, B4[nt].z, B4[nt].w);
    }

    // ---- denominators: quad-reduce per row ----
#pragma unroll
    for (int k = 0; k < 2; ++k) {
        den2[k] += __shfl_xor_sync(0xffffffffu, den2[k], 1);
        den2[k] += __shfl_xor_sync(0xffffffffu, den2[k], 2);
    }
    if ((l & 3) == 0) {
        g_pden[split][i0 + w * 16 + rq]     = den2[0];
        g_pden[split][i0 + w * 16 + 8 + rq] = den2[1];
    }

    // ---- write fp32 partial numerators ----
    {
        const int row = i0 + w * 16 + rq;
#pragma unroll
        for (int n = 0; n < 8; ++n) {
            *(float2*)&g_pacc[split][row][n * 8 + cq]     = make_float2(acc[n][0], acc[n][1]);
            *(float2*)&g_pacc[split][row + 8][n * 8 + cq] = make_float2(acc[n][2], acc[n][3]);
        }
    }
}

// ---------------------------------------------------------------------------
// Kernel 3: combine splits, normalize, ELU (float4-vectorized).
// ---------------------------------------------------------------------------
__global__ void __launch_bounds__(256) combine_kernel(float* __restrict__ out) {
    const int idx4 = blockIdx.x * 256 + threadIdx.x;   // over 8192*16
    const int i = idx4 >> 4;
    const int c4 = idx4 & 15;
    float4 acc = make_float4(0.f, 0.f, 0.f, 0.f);
    float den = 0.f;
#pragma unroll
    for (int sp = 0; sp < JSPLITS; ++sp) {
        float4 v = *(const float4*)&g_pacc[sp][i][c4 * 4];
        acc.x += v.x; acc.y += v.y; acc.z += v.z; acc.w += v.w;
        den += g_pden[sp][i];
    }
    if (den == 0.f) den = 1.f;
    float inv = 1.f / den;
    float4 o;
    o.x = acc.x * inv; o.x = o.x > 0.f ? o.x : expm1f(o.x);
    o.y = acc.y * inv; o.y = o.y > 0.f ? o.y : expm1f(o.y);
    o.z = acc.z * inv; o.z = o.z > 0.f ? o.z : expm1f(o.z);
    o.w = acc.w * inv; o.w = o.w > 0.f ? o.w : expm1f(o.w);
    *(float4*)&out[idx4 * 4] = o;
}

// ---------------------------------------------------------------------------
extern "C" void kernel_launch(void* const* d_in, const int* in_sizes, int n_in,
                              void* d_out, int out_size) {
    const float* h   = (const float*)d_in[0];
    const float* W   = (const float*)d_in[1];
    const float* a   = (const float*)d_in[2];
    const int*   adj = (const int*)d_in[3];
    float* out = (float*)d_out;

    prep_w<<<32, 256>>>(W);
    wh_mma<<<128, 128>>>(h, a);
    attn_kernel<<<(NN / 128) * JSPLITS, 256>>>(adj);
    combine_kernel<<<NN * 16 / 256, 256>>>(out);
}

// round 9
// speedup vs baseline: 1.1435x; 1.0929x over previous
#include <cuda_runtime.h>
#include <cuda_bf16.h>
#include <cuda_fp16.h>
#include <cstdint>

#define NN      8192
#define F_IN    512
#define NOUT    64
#define LRA     0.2f
#define JSPLITS 8
#define JLEN    (NN / JSPLITS)     // 1024
#define NCH     (JLEN / 16)        // 64 chunks of k=16
#define NBLK    (NCH / 2)          // 32 blocks of k=32
#define BST     80                 // padded bytes per n-row in staged B
#define BBUF    (64 * BST)         // 5120 B per (stage,hi/lo)

// ---------------- device scratch (no cudaMalloc allowed) -------------------
__device__ uint4 g_W_pk[64 * 32 * 4];           // 128 KB (bf16 frags for wh GEMM)
__device__ __align__(16) __half g_WhT_hi[NOUT * NN];   // fp16 hi, [n][j] K-major
__device__ __align__(16) __half g_WhT_lo[NOUT * NN];   // fp16 lo
__device__ float g_e1[NN];
__device__ float g_e2[NN];
__device__ float g_m2;                          // max_j e2[j]
__device__ float g_pacc[JSPLITS][NN][NOUT];
__device__ float g_pden[JSPLITS][NN];

// ---------------- helpers ---------------------------------------------------
__device__ __forceinline__ void mma_bf16(float* d, const unsigned* a,
                                         unsigned b0, unsigned b1) {
    asm volatile(
        "mma.sync.aligned.m16n8k16.row.col.f32.bf16.bf16.f32 "
        "{%0,%1,%2,%3}, {%4,%5,%6,%7}, {%8,%9}, {%0,%1,%2,%3};"
        : "+f"(d[0]), "+f"(d[1]), "+f"(d[2]), "+f"(d[3])
        : "r"(a[0]), "r"(a[1]), "r"(a[2]), "r"(a[3]), "r"(b0), "r"(b1));
}
__device__ __forceinline__ void mma_f16(float* d, const unsigned* a,
                                        unsigned b0, unsigned b1) {
    asm volatile(
        "mma.sync.aligned.m16n8k16.row.col.f32.f16.f16.f32 "
        "{%0,%1,%2,%3}, {%4,%5,%6,%7}, {%8,%9}, {%0,%1,%2,%3};"
        : "+f"(d[0]), "+f"(d[1]), "+f"(d[2]), "+f"(d[3])
        : "r"(a[0]), "r"(a[1]), "r"(a[2]), "r"(a[3]), "r"(b0), "r"(b1));
}
__device__ __forceinline__ void ldsm4(unsigned* r, uint32_t addr) {
    asm volatile("ldmatrix.sync.aligned.m8n8.x4.shared.b16 {%0,%1,%2,%3}, [%4];"
                 : "=r"(r[0]), "=r"(r[1]), "=r"(r[2]), "=r"(r[3]) : "r"(addr));
}
__device__ __forceinline__ unsigned cvt2b(float po, float pe) {  // bf16x2, lo=pe
    unsigned r;
    asm("cvt.rn.bf16x2.f32 %0, %1, %2;" : "=r"(r) : "f"(po), "f"(pe));
    return r;
}
__device__ __forceinline__ unsigned cvt2h(float po, float pe) {  // f16x2, lo=pe
    unsigned r;
    asm("cvt.rn.f16x2.f32 %0, %1, %2;" : "=r"(r) : "f"(po), "f"(pe));
    return r;
}
__device__ __forceinline__ float bfhf(float x) {
    return __bfloat162float(__float2bfloat16_rn(x));
}
__device__ __forceinline__ uint32_t smem_u32(const void* p) {
    return (uint32_t)__cvta_generic_to_shared(p);
}
__device__ __forceinline__ void cpa16(uint32_t dst, const void* src) {
    asm volatile("cp.async.cg.shared.global [%0], [%1], 16;" :: "r"(dst), "l"(src));
}
__device__ __forceinline__ void cpcommit() {
    asm volatile("cp.async.commit_group;" ::: "memory");
}
template <int N> __device__ __forceinline__ void cpwait() {
    asm volatile("cp.async.wait_group %0;" :: "n"(N) : "memory");
}

// ---------------------------------------------------------------------------
// Kernel 0: pack W (fp32 [512][64]) into bf16 hi/lo fragment layout (wh GEMM).
// ---------------------------------------------------------------------------
__global__ void __launch_bounds__(256) prep_w(const float* __restrict__ W) {
    const int t = blockIdx.x * 256 + threadIdx.x;
    const int s = t & 3, kc = (t >> 2) & 31, n = t >> 7;
    const int k0 = kc * 16 + 2 * s;
    float v00 = W[(k0 + 0) * 64 + n], v01 = W[(k0 + 1) * 64 + n];
    float v10 = W[(k0 + 8) * 64 + n], v11 = W[(k0 + 9) * 64 + n];
    float h00 = bfhf(v00), h01 = bfhf(v01), h10 = bfhf(v10), h11 = bfhf(v11);
    uint4 o;
    o.x = cvt2b(h01, h00);
    o.y = cvt2b(h11, h10);
    o.z = cvt2b(v01 - h01, v00 - h00);
    o.w = cvt2b(v11 - h11, v10 - h10);
    g_W_pk[(n * 32 + kc) * 4 + s] = o;
}

// ---------------------------------------------------------------------------
// Kernel 1: Wh = h @ W via mma.sync (3-product bf16 split, proven numerics).
// Epilogue: e1/e2, then WhT packed as fp16 hi/lo row-major [n][j].
// ---------------------------------------------------------------------------
__global__ void __launch_bounds__(128, 1) wh_mma(const float* __restrict__ h,
                                                 const float* __restrict__ a) {
    __shared__ float s_h[3][64][20];
    __shared__ float s_t[64][65];

    const int tid = threadIdx.x;
    const int w = tid >> 5;
    const int l = tid & 31;
    const int r = l >> 2;
    const int c = (l & 3) * 2;
    const int node0 = blockIdx.x * 64;

    const uint32_t shb = smem_u32(&s_h[0][0][0]);
    auto stage = [&](int kc, int s) {
        const int row = tid >> 1, half = tid & 1;
        const float* src = h + (size_t)(node0 + row) * F_IN + kc * 16 + half * 8;
        uint32_t dst = shb + (uint32_t)((s * 64 + row) * 20 + half * 8) * 4;
        cpa16(dst, src);
        cpa16(dst + 16, src + 4);
    };

    stage(0, 0); cpcommit();
    stage(1, 1); cpcommit();

    float acc[8][4];
#pragma unroll
    for (int n = 0; n < 8; ++n)
#pragma unroll
        for (int q = 0; q < 4; ++q) acc[n][q] = 0.f;

    const uint4* __restrict__ wpk = g_W_pk;

    for (int kc = 0; kc < 32; ++kc) {
        const int ss = kc % 3;
        if (kc + 1 < 32) cpwait<1>(); else cpwait<0>();
        __syncthreads();
        if (kc + 2 < 32) { stage(kc + 2, (kc + 2) % 3); cpcommit(); }

        uint4 B4[8];
#pragma unroll
        for (int nt = 0; nt < 8; ++nt)
            B4[nt] = wpk[((nt * 8 + r) * 32 + kc) * 4 + (l & 3)];

        float2 v0 = *(const float2*)&s_h[ss][w * 16 + r][c];
        float2 v1 = *(const float2*)&s_h[ss][w * 16 + r + 8][c];
        float2 v2 = *(const float2*)&s_h[ss][w * 16 + r][c + 8];
        float2 v3 = *(const float2*)&s_h[ss][w * 16 + r + 8][c + 8];
        float h0x = bfhf(v0.x), h0y = bfhf(v0.y);
        float h1x = bfhf(v1.x), h1y = bfhf(v1.y);
        float h2x = bfhf(v2.x), h2y = bfhf(v2.y);
        float h3x = bfhf(v3.x), h3y = bfhf(v3.y);
        unsigned Ah[4], Al[4];
        Ah[0] = cvt2b(h0y, h0x); Al[0] = cvt2b(v0.y - h0y, v0.x - h0x);
        Ah[1] = cvt2b(h1y, h1x); Al[1] = cvt2b(v1.y - h1y, v1.x - h1x);
        Ah[2] = cvt2b(h2y, h2x); Al[2] = cvt2b(v2.y - h2y, v2.x - h2x);
        Ah[3] = cvt2b(h3y, h3x); Al[3] = cvt2b(v3.y - h3y, v3.x - h3x);

#pragma unroll
        for (int nt = 0; nt < 8; ++nt) mma_bf16(acc[nt], Ah, B4[nt].x, B4[nt].y);
#pragma unroll
        for (int nt = 0; nt < 8; ++nt) mma_bf16(acc[nt], Al, B4[nt].x, B4[nt].y);
#pragma unroll
        for (int nt = 0; nt < 8; ++nt) mma_bf16(acc[nt], Ah, B4[nt].z, B4[nt].w);
    }

    {
        float e1p0 = 0.f, e1p8 = 0.f, e2p0 = 0.f, e2p8 = 0.f;
#pragma unroll
        for (int nt = 0; nt < 8; ++nt) {
            float2 a1v = *(const float2*)&a[nt * 8 + c];
            float2 a2v = *(const float2*)&a[NOUT + nt * 8 + c];
            e1p0 += acc[nt][0] * a1v.x + acc[nt][1] * a1v.y;
            e1p8 += acc[nt][2] * a1v.x + acc[nt][3] * a1v.y;
            e2p0 += acc[nt][0] * a2v.x + acc[nt][1] * a2v.y;
            e2p8 += acc[nt][2] * a2v.x + acc[nt][3] * a2v.y;
        }
#pragma unroll
        for (int off = 1; off <= 2; off <<= 1) {
            e1p0 += __shfl_xor_sync(0xffffffffu, e1p0, off);
            e1p8 += __shfl_xor_sync(0xffffffffu, e1p8, off);
            e2p0 += __shfl_xor_sync(0xffffffffu, e2p0, off);
            e2p8 += __shfl_xor_sync(0xffffffffu, e2p8, off);
        }
        if ((l & 3) == 0) {
            g_e1[node0 + w * 16 + r]     = e1p0;
            g_e1[node0 + w * 16 + r + 8] = e1p8;
            g_e2[node0 + w * 16 + r]     = e2p0;
            g_e2[node0 + w * 16 + r + 8] = e2p8;
        }
    }

    __syncthreads();
#pragma unroll
    for (int nt = 0; nt < 8; ++nt) {
        s_t[w * 16 + r][nt * 8 + c]         = acc[nt][0];
        s_t[w * 16 + r][nt * 8 + c + 1]     = acc[nt][1];
        s_t[w * 16 + r + 8][nt * 8 + c]     = acc[nt][2];
        s_t[w * 16 + r + 8][nt * 8 + c + 1] = acc[nt][3];
    }
    __syncthreads();

    // pack WhT as fp16 hi/lo: thread -> (col n, half nh), 32 j's contiguous
    {
        const int col = tid >> 1, nh = tid & 1;
        float f[32];
#pragma unroll
        for (int j = 0; j < 32; ++j) f[j] = s_t[nh * 32 + j][col];
        unsigned hw[16], lw[16];
#pragma unroll
        for (int q = 0; q < 16; ++q) {
            float f0 = f[2 * q], f1 = f[2 * q + 1];
            float g0 = __half2float(__float2half_rn(f0));
            float g1 = __half2float(__float2half_rn(f1));
            hw[q] = cvt2h(g1, g0);
            lw[q] = cvt2h(f1 - g1, f0 - g0);
        }
        const size_t base = (size_t)col * NN + blockIdx.x * 64 + nh * 32;
        uint4* dh = (uint4*)(g_WhT_hi + base);
        uint4* dl = (uint4*)(g_WhT_lo + base);
#pragma unroll
        for (int q = 0; q < 4; ++q) {
            dh[q] = *(uint4*)&hw[4 * q];
            dl[q] = *(uint4*)&lw[4 * q];
        }
    }
}

// ---------------------------------------------------------------------------
// Kernel 1.5: global max of e2 (single CTA).
// ---------------------------------------------------------------------------
__global__ void __launch_bounds__(256) e2max_kernel() {
    __shared__ float sm[8];
    const int tid = threadIdx.x;
    float m = -1e30f;
    for (int k = tid; k < NN; k += 256) m = fmaxf(m, g_e2[k]);
#pragma unroll
    for (int off = 16; off; off >>= 1)
        m = fmaxf(m, __shfl_xor_sync(0xffffffffu, m, off));
    if ((tid & 31) == 0) sm[tid >> 5] = m;
    __syncthreads();
    if (tid == 0) {
        float mm = sm[0];
#pragma unroll
        for (int q = 1; q < 8; ++q) mm = fmaxf(mm, sm[q]);
        g_m2 = mm;
    }
}

// ---------------------------------------------------------------------------
// Kernel 2: fused masked-exp + fp16 2-product GEMM via mma.sync.
// p = exp(lrelu(e1+e2) - M_i) in (0,1] -> single fp16 A fragment;
// Wh as fp16 hi+lo (B). 16 HMMA/chunk (was 24). B staged via 3-stage cp.async
// + ldmatrix (R5-proven path). den carries the same exp(-M_i) scale.
// ---------------------------------------------------------------------------
__global__ void __launch_bounds__(256, 2) attn_kernel(const int* __restrict__ adj) {
    __shared__ float s_e2[JLEN];                          // 4 KB
    __shared__ __align__(16) char s_B[3][2][BBUF];        // 30 KB

    const int tid = threadIdx.x;
    const int w = tid >> 5;
    const int l = tid & 31;
    const int i0 = (int)(blockIdx.x >> 3) * 128;
    const int split = blockIdx.x & 7;
    const int j0 = split * JLEN;

    {
        float4* d = (float4*)s_e2;
        const float4* s = (const float4*)(g_e2 + j0);
        for (int k = tid; k < JLEN / 4; k += 256) d[k] = s[k];
    }

    const int rq = l >> 2;          // 0..7
    const int cq = (l & 3) * 2;     // 0,2,4,6
    const float M2 = g_m2;

    float e1r[2], mi[2];
    const int* rb[2];
#pragma unroll
    for (int k = 0; k < 2; ++k) {
        int row = i0 + w * 16 + 8 * k + rq;
        e1r[k] = g_e1[row];
        float mv = e1r[k] + M2;
        mi[k] = mv > 0.f ? mv : LRA * mv;   // lrelu(e1+max e2) = row max logit
        rb[k] = adj + (size_t)row * NN + j0 + cq;
    }

    const uint32_t sBs = smem_u32(&s_B[0][0][0]);
    auto stage = [&](int blk, int s) {
#pragma unroll
        for (int it = 0; it < 2; ++it) {
            int idx = it * 256 + tid;            // 0..511
            int hl = idx >> 8;                   // 0:hi 1:lo
            int rem = idx & 255;
            int c = rem >> 6;                    // 16B chunk 0..3 (8 halves)
            int n = rem & 63;                    // n-row
            const __half* src =
                (hl ? g_WhT_lo : g_WhT_hi) + (size_t)n * NN + j0 + blk * 32 + c * 8;
            cpa16(sBs + (uint32_t)((s * 2 + hl) * BBUF + n * BST + c * 16), src);
        }
    };

    const int g = l >> 3, lr = l & 7;
    const uint32_t sBm = sBs + (uint32_t)((lr + ((g >> 1) << 3)) * BST + ((g & 1) << 4));

    float acc[8][4];
#pragma unroll
    for (int n = 0; n < 8; ++n)
#pragma unroll
        for (int q = 0; q < 4; ++q) acc[n][q] = 0.f;
    float den2[2] = {0.f, 0.f};

    stage(0, 0); cpcommit();
    stage(1, 1); cpcommit();
    int2 alo[2], ahi[2];
#pragma unroll
    for (int k = 0; k < 2; ++k) {
        alo[k] = *(const int2*)(rb[k]);
        ahi[k] = *(const int2*)(rb[k] + 8);
    }

    for (int blk = 0; blk < NBLK; ++blk) {
        const int s = blk % 3;
        if (blk + 1 < NBLK) cpwait<1>(); else cpwait<0>();
        __syncthreads();
        if (blk + 2 < NBLK) { stage(blk + 2, (blk + 2) % 3); cpcommit(); }

#pragma unroll
        for (int c2 = 0; c2 < 2; ++c2) {
            const int ch = blk * 2 + c2;

            // ---- A fragments: shifted masked exp, fp16, single product ----
            const float* e2p = s_e2 + ch * 16;
            float2 e2a = *(const float2*)(e2p + cq);
            float2 e2b = *(const float2*)(e2p + cq + 8);
            unsigned Ah[4];
#pragma unroll
            for (int k = 0; k < 2; ++k) {
                const float e1v = e1r[k];
                float s0 = e1v + e2a.x; s0 = (s0 > 0.f ? s0 : LRA * s0) - mi[k];
                float s1 = e1v + e2a.y; s1 = (s1 > 0.f ? s1 : LRA * s1) - mi[k];
                float s2 = e1v + e2b.x; s2 = (s2 > 0.f ? s2 : LRA * s2) - mi[k];
                float s3 = e1v + e2b.y; s3 = (s3 > 0.f ? s3 : LRA * s3) - mi[k];
                float p0 = alo[k].x > 0 ? __expf(s0) : 0.f;
                float p1 = alo[k].y > 0 ? __expf(s1) : 0.f;
                float p2 = ahi[k].x > 0 ? __expf(s2) : 0.f;
                float p3 = ahi[k].y > 0 ? __expf(s3) : 0.f;
                den2[k] += (p0 + p1) + (p2 + p3);
                Ah[k]     = cvt2h(p1, p0);
                Ah[k + 2] = cvt2h(p3, p2);
            }

            // ---- prefetch next chunk's adj ----
            if (ch + 1 < NCH) {
#pragma unroll
                for (int k = 0; k < 2; ++k) {
                    alo[k] = *(const int2*)(rb[k] + (ch + 1) * 16);
                    ahi[k] = *(const int2*)(rb[k] + (ch + 1) * 16 + 8);
                }
            }

            // ---- B hi fragments + product ----
            const uint32_t bo_hi = (uint32_t)((s * 2) * BBUF + c2 * 32);
            unsigned Bh[8][2];
#pragma unroll
            for (int np = 0; np < 4; ++np)
                ldsm4(&Bh[2 * np][0], sBm + bo_hi + np * (16 * BST));
#pragma unroll
            for (int n = 0; n < 8; ++n) mma_f16(acc[n], Ah, Bh[n][0], Bh[n][1]);

            // ---- B lo fragments + product ----
            const uint32_t bo_lo = (uint32_t)((s * 2 + 1) * BBUF + c2 * 32);
            unsigned Bl[8][2];
#pragma unroll
            for (int np = 0; np < 4; ++np)
                ldsm4(&Bl[2 * np][0], sBm + bo_lo + np * (16 * BST));
#pragma unroll
            for (int n = 0; n < 8; ++n) mma_f16(acc[n], Ah, Bl[n][0], Bl[n][1]);
        }
    }

    // ---- denominators: quad-reduce per row ----
#pragma unroll
    for (int k = 0; k < 2; ++k) {
        den2[k] += __shfl_xor_sync(0xffffffffu, den2[k], 1);
        den2[k] += __shfl_xor_sync(0xffffffffu, den2[k], 2);
    }
    if ((l & 3) == 0) {
        g_pden[split][i0 + w * 16 + rq]     = den2[0];
        g_pden[split][i0 + w * 16 + 8 + rq] = den2[1];
    }

    // ---- write fp32 partial numerators ----
    {
        const int row = i0 + w * 16 + rq;
#pragma unroll
        for (int n = 0; n < 8; ++n) {
            *(float2*)&g_pacc[split][row][n * 8 + cq]     = make_float2(acc[n][0], acc[n][1]);
            *(float2*)&g_pacc[split][row + 8][n * 8 + cq] = make_float2(acc[n][2], acc[n][3]);
        }
    }
}

// ---------------------------------------------------------------------------
// Kernel 3: combine splits, normalize, ELU (float4-vectorized).
// ---------------------------------------------------------------------------
__global__ void __launch_bounds__(256) combine_kernel(float* __restrict__ out) {
    const int idx4 = blockIdx.x * 256 + threadIdx.x;   // over 8192*16
    const int i = idx4 >> 4;
    const int c4 = idx4 & 15;
    float4 acc = make_float4(0.f, 0.f, 0.f, 0.f);
    float den = 0.f;
#pragma unroll
    for (int sp = 0; sp < JSPLITS; ++sp) {
        float4 v = *(const float4*)&g_pacc[sp][i][c4 * 4];
        acc.x += v.x; acc.y += v.y; acc.z += v.z; acc.w += v.w;
        den += g_pden[sp][i];
    }
    if (den == 0.f) den = 1.f;
    float inv = 1.f / den;
    float4 o;
    o.x = acc.x * inv; o.x = o.x > 0.f ? o.x : expm1f(o.x);
    o.y = acc.y * inv; o.y = o.y > 0.f ? o.y : expm1f(o.y);
    o.z = acc.z * inv; o.z = o.z > 0.f ? o.z : expm1f(o.z);
    o.w = acc.w * inv; o.w = o.w > 0.f ? o.w : expm1f(o.w);
    *(float4*)&out[idx4 * 4] = o;
}

// ---------------------------------------------------------------------------
extern "C" void kernel_launch(void* const* d_in, const int* in_sizes, int n_in,
                              void* d_out, int out_size) {
    const float* h   = (const float*)d_in[0];
    const float* W   = (const float*)d_in[1];
    const float* a   = (const float*)d_in[2];
    const int*   adj = (const int*)d_in[3];
    float* out = (float*)d_out;

    prep_w<<<32, 256>>>(W);
    wh_mma<<<128, 128>>>(h, a);
    e2max_kernel<<<1, 256>>>();
    attn_kernel<<<(NN / 128) * JSPLITS, 256>>>(adj);
    combine_kernel<<<NN * 16 / 256, 256>>>(out);
}